// round 1
// baseline (speedup 1.0000x reference)
#include <cuda_runtime.h>
#include <math.h>

#define Bsz 2
#define Tt  2048
#define Cc  1024
#define Hh  16
#define KVh 4
#define HDim 64
// n_rep = Hh/KVh = 4

// -------- scratch (static device globals; no allocation) --------
__device__ float g_Q[Bsz * Tt * Hh * HDim];    // 16 MB
__device__ float g_K[Bsz * Tt * KVh * HDim];   // 4 MB
__device__ float g_V[Bsz * Tt * KVh * HDim];   // 4 MB
__device__ float g_Y[Bsz * Tt * Hh * HDim];    // 16 MB

// ============================================================
// Classic 128x128x8 SGEMM, row-major A[M,K] @ B[K,N] -> C[M,N]
// Requires M%128==0, N%128==0, K%8==0 (true for all our shapes)
// ============================================================
__global__ __launch_bounds__(256) void sgemm128(
    const float* __restrict__ A, const float* __restrict__ B,
    float* __restrict__ C, int M, int N, int K)
{
    const int BM = 128, BN = 128, BK = 8;
    __shared__ float As[BK][BM];
    __shared__ float Bs[BK][BN];

    int tid = threadIdx.x;
    int bm = blockIdx.y * BM;
    int bn = blockIdx.x * BN;
    int tx = tid & 15;        // 0..15 -> 8 cols each
    int ty = tid >> 4;        // 0..15 -> 8 rows each

    int arow = tid >> 1;              // 0..127
    int acol = (tid & 1) * 4;         // 0 or 4
    int brow = tid >> 5;              // 0..7
    int bcol = (tid & 31) * 4;        // 0..124

    const float* Aptr = A + (size_t)(bm + arow) * K + acol;
    const float* Bptr = B + (size_t)brow * N + bn + bcol;

    float acc[8][8];
#pragma unroll
    for (int i = 0; i < 8; i++)
#pragma unroll
        for (int j = 0; j < 8; j++) acc[i][j] = 0.f;

    for (int k0 = 0; k0 < K; k0 += BK) {
        float4 a4 = *(const float4*)(Aptr + k0);
        float4 b4 = *(const float4*)(Bptr + (size_t)k0 * N);
        As[acol + 0][arow] = a4.x;
        As[acol + 1][arow] = a4.y;
        As[acol + 2][arow] = a4.z;
        As[acol + 3][arow] = a4.w;
        *(float4*)&Bs[brow][bcol] = b4;
        __syncthreads();

#pragma unroll
        for (int k = 0; k < BK; k++) {
            float ar[8], br[8];
            *(float4*)(ar)     = *(const float4*)&As[k][ty * 8];
            *(float4*)(ar + 4) = *(const float4*)&As[k][ty * 8 + 4];
            *(float4*)(br)     = *(const float4*)&Bs[k][tx * 8];
            *(float4*)(br + 4) = *(const float4*)&Bs[k][tx * 8 + 4];
#pragma unroll
            for (int i = 0; i < 8; i++)
#pragma unroll
                for (int j = 0; j < 8; j++)
                    acc[i][j] += ar[i] * br[j];
        }
        __syncthreads();
    }

#pragma unroll
    for (int i = 0; i < 8; i++) {
        float* cp = C + (size_t)(bm + ty * 8 + i) * N + bn + tx * 8;
        *(float4*)cp       = make_float4(acc[i][0], acc[i][1], acc[i][2], acc[i][3]);
        *(float4*)(cp + 4) = make_float4(acc[i][4], acc[i][5], acc[i][6], acc[i][7]);
    }
}

// ============================================================
// RoPE + RMSNorm, one warp per (row, head). In-place on Q and K.
// Q rows enumerated first (B*T*H), then K rows (B*T*KV).
// ============================================================
__global__ __launch_bounds__(256) void rope_rms(
    float* __restrict__ Q, float* __restrict__ K,
    const float* __restrict__ cosp, const float* __restrict__ sinp)
{
    int gw = (blockIdx.x * blockDim.x + threadIdx.x) >> 5;
    int lane = threadIdx.x & 31;
    const int total_q = Bsz * Tt * Hh;

    float* p;
    int t;
    if (gw < total_q) {
        t = (gw / Hh) % Tt;
        p = Q + (size_t)gw * HDim;
    } else {
        int g = gw - total_q;
        t = (g / KVh) % Tt;
        p = K + (size_t)g * HDim;
    }

    float c = cosp[t * (HDim / 2) + lane];
    float s = sinp[t * (HDim / 2) + lane];
    float x1 = p[lane];
    float x2 = p[lane + 32];
    float o1 = x1 * c + x2 * s;
    float o2 = -x1 * s + x2 * c;

    float ss = o1 * o1 + o2 * o2;
#pragma unroll
    for (int off = 16; off > 0; off >>= 1)
        ss += __shfl_xor_sync(0xffffffffu, ss, off);

    float inv = rsqrtf(ss * (1.0f / HDim) + 1e-6f);
    p[lane]      = o1 * inv;
    p[lane + 32] = o2 * inv;
}

// ============================================================
// Causal GQA flash attention.
// grid = (T/64, H, B), block = 64 threads. Thread t owns q row q0+t.
// K/V tiles (64x64) staged in smem; S stored transposed S[j][t].
// ============================================================
__global__ __launch_bounds__(64) void flash_attn(
    const float* __restrict__ Qg, const float* __restrict__ Kg,
    const float* __restrict__ Vg, float* __restrict__ Og)
{
    __shared__ float Ks[64 * 64];
    __shared__ float Vs[64 * 64];
    __shared__ float Ss[64 * 64];   // also used as Q staging / O staging

    int qb = blockIdx.x;
    int h  = blockIdx.y;
    int b  = blockIdx.z;
    int t  = threadIdx.x;          // 0..63
    int kvh = h >> 2;              // h / n_rep
    int q0 = qb * 64;

    // ---- stage Q tile coalesced, then pull own row into registers ----
    const float* Qbase = Qg + ((size_t)(b * Tt + q0) * Hh + h) * HDim;
#pragma unroll
    for (int i = 0; i < 16; i++) {
        int fi = i * 64 + t;           // float4 index 0..1023
        int row = fi >> 4, c4 = fi & 15;
        *(float4*)&Ss[row * 64 + c4 * 4] =
            *(const float4*)(Qbase + (size_t)row * (Hh * HDim) + c4 * 4);
    }
    __syncthreads();

    float4 q[16];
#pragma unroll
    for (int i = 0; i < 16; i++) q[i] = *(const float4*)&Ss[t * 64 + i * 4];
    __syncthreads();

    float4 o[16];
#pragma unroll
    for (int i = 0; i < 16; i++) o[i] = make_float4(0.f, 0.f, 0.f, 0.f);
    float m = -1e30f, l = 0.f;

    const float* Kbase = Kg + ((size_t)(b * Tt) * KVh + kvh) * HDim;
    const float* Vbase = Vg + ((size_t)(b * Tt) * KVh + kvh) * HDim;

    for (int kt = 0; kt <= qb; kt++) {
        // load K,V tiles coalesced
#pragma unroll
        for (int i = 0; i < 16; i++) {
            int fi = i * 64 + t;
            int row = fi >> 4, c4 = fi & 15;
            size_t g = (size_t)(kt * 64 + row) * (KVh * HDim) + c4 * 4;
            *(float4*)&Ks[row * 64 + c4 * 4] = *(const float4*)(Kbase + g);
            *(float4*)&Vs[row * 64 + c4 * 4] = *(const float4*)(Vbase + g);
        }
        __syncthreads();

        int jmax = (kt == qb) ? t : 63;
        float tmax = -1e30f;

        // pass 1: scores
        for (int j = 0; j < 64; j++) {
            float s;
            if (j <= jmax) {
                float a0 = 0.f, a1 = 0.f, a2 = 0.f, a3 = 0.f;
                const float4* kr = (const float4*)(Ks + j * 64);
#pragma unroll
                for (int i = 0; i < 16; i++) {
                    float4 k4 = kr[i];
                    a0 += q[i].x * k4.x;
                    a1 += q[i].y * k4.y;
                    a2 += q[i].z * k4.z;
                    a3 += q[i].w * k4.w;
                }
                s = ((a0 + a1) + (a2 + a3)) * 0.125f;   // 1/sqrt(64)
                tmax = fmaxf(tmax, s);
            } else {
                s = -1e30f;
            }
            Ss[j * 64 + t] = s;
        }

        float mn = fmaxf(m, tmax);
        float corr = __expf(m - mn);
        m = mn;
        l *= corr;
#pragma unroll
        for (int i = 0; i < 16; i++) {
            o[i].x *= corr; o[i].y *= corr; o[i].z *= corr; o[i].w *= corr;
        }

        // pass 2: probs * V
        for (int j = 0; j <= jmax; j++) {
            float p = __expf(Ss[j * 64 + t] - mn);
            l += p;
            const float4* vr = (const float4*)(Vs + j * 64);
#pragma unroll
            for (int i = 0; i < 16; i++) {
                float4 v4 = vr[i];
                o[i].x += p * v4.x;
                o[i].y += p * v4.y;
                o[i].z += p * v4.z;
                o[i].w += p * v4.w;
            }
        }
        __syncthreads();
    }

    // normalize and write out (stage through smem for coalescing)
    float inv = 1.f / l;
#pragma unroll
    for (int i = 0; i < 16; i++) {
        o[i].x *= inv; o[i].y *= inv; o[i].z *= inv; o[i].w *= inv;
        *(float4*)&Ss[t * 64 + i * 4] = o[i];
    }
    __syncthreads();

    float* Obase = Og + ((size_t)(b * Tt + q0) * Hh + h) * HDim;
#pragma unroll
    for (int i = 0; i < 16; i++) {
        int fi = i * 64 + t;
        int row = fi >> 4, c4 = fi & 15;
        *(float4*)(Obase + (size_t)row * (Hh * HDim) + c4 * 4) =
            *(const float4*)&Ss[row * 64 + c4 * 4];
    }
}

// ============================================================
// launch
// ============================================================
extern "C" void kernel_launch(void* const* d_in, const int* in_sizes, int n_in,
                              void* d_out, int out_size)
{
    const float* x  = (const float*)d_in[0];
    const float* cs = (const float*)d_in[1];
    const float* sn = (const float*)d_in[2];
    const float* Wq = (const float*)d_in[3];
    const float* Wk = (const float*)d_in[4];
    const float* Wv = (const float*)d_in[5];
    const float* Wo = (const float*)d_in[6];
    float* out = (float*)d_out;

    float *Qp, *Kp, *Vp, *Yp;
    cudaGetSymbolAddress((void**)&Qp, g_Q);
    cudaGetSymbolAddress((void**)&Kp, g_K);
    cudaGetSymbolAddress((void**)&Vp, g_V);
    cudaGetSymbolAddress((void**)&Yp, g_Y);

    const int M = Bsz * Tt;  // 4096

    // QKV projections
    sgemm128<<<dim3((Hh * HDim) / 128, M / 128), 256>>>(x, Wq, Qp, M, Hh * HDim, Cc);
    sgemm128<<<dim3((KVh * HDim) / 128, M / 128), 256>>>(x, Wk, Kp, M, KVh * HDim, Cc);
    sgemm128<<<dim3((KVh * HDim) / 128, M / 128), 256>>>(x, Wv, Vp, M, KVh * HDim, Cc);

    // RoPE + RMSNorm on Q and K
    {
        int warps = M * (Hh + KVh);             // 81920
        int threads = warps * 32;               // 2,621,440
        rope_rms<<<threads / 256, 256>>>(Qp, Kp, cs, sn);
    }

    // causal GQA flash attention
    flash_attn<<<dim3(Tt / 64, Hh, Bsz), 64>>>(Qp, Kp, Vp, Yp);

    // output projection
    sgemm128<<<dim3(Cc / 128, M / 128), 256>>>(Yp, Wo, out, M, Cc, Cc);
}

// round 3
// speedup vs baseline: 1.4524x; 1.4524x over previous
#include <cuda_runtime.h>
#include <math.h>
#include <stdint.h>

#define Bsz 2
#define Tt  2048
#define Cc  1024
#define Hh  16
#define KVh 4
#define HDim 64

// -------- scratch (static device globals; no allocation) --------
__device__ float g_Q[Bsz * Tt * Hh * HDim];
__device__ float g_K[Bsz * Tt * KVh * HDim];
__device__ float g_V[Bsz * Tt * KVh * HDim];
__device__ float g_Y[Bsz * Tt * Hh * HDim];
__device__ float g_WqT[Cc * Hh * HDim];
__device__ float g_WkT[Cc * KVh * HDim];
__device__ float g_WvT[Cc * KVh * HDim];
__device__ float g_WoT[Cc * Cc];

__device__ __forceinline__ uint32_t f2tf32(float f) {
    uint32_t r;
    asm("cvt.rna.tf32.f32 %0, %1;" : "=r"(r) : "f"(f));
    return r;
}

__device__ __forceinline__ void mma_tf32(float* c, const uint32_t* a, const uint32_t* b) {
    asm volatile(
        "mma.sync.aligned.m16n8k8.row.col.f32.tf32.tf32.f32 "
        "{%0,%1,%2,%3}, {%4,%5,%6,%7}, {%8,%9}, {%0,%1,%2,%3};"
        : "+f"(c[0]), "+f"(c[1]), "+f"(c[2]), "+f"(c[3])
        : "r"(a[0]), "r"(a[1]), "r"(a[2]), "r"(a[3]), "r"(b[0]), "r"(b[1]));
}

// ============================================================
// Weight transpose: in[K,N] -> out[N,K]
// ============================================================
__global__ __launch_bounds__(256) void transpose_k(
    const float* __restrict__ in, float* __restrict__ out, int K, int N)
{
    __shared__ float tile[32][33];
    int k0 = blockIdx.y * 32, n0 = blockIdx.x * 32;
    int tx = threadIdx.x, ty = threadIdx.y;   // 32 x 8
#pragma unroll
    for (int i = 0; i < 32; i += 8)
        tile[ty + i][tx] = in[(size_t)(k0 + ty + i) * N + n0 + tx];
    __syncthreads();
#pragma unroll
    for (int i = 0; i < 32; i += 8)
        out[(size_t)(n0 + ty + i) * K + k0 + tx] = tile[tx][ty + i];
}

// ============================================================
// tf32 mma.sync GEMM: C[M,N] = A[M,K] @ BT[N,K]^T
// 128x128 CTA tile, 256 threads (8 warps, 2m x 4n), K-chunk 32.
// Requires M%128==0, N%128==0, K%32==0.
// ============================================================
#define SMS 36   // smem row stride (floats): lane -> bank bijective

__global__ __launch_bounds__(256, 2) void gemm_mma(
    const float* __restrict__ A, const float* __restrict__ BT,
    float* __restrict__ C, int M, int N, int K)
{
    __shared__ float As[128 * SMS];
    __shared__ float Bs[128 * SMS];

    int tid = threadIdx.x;
    int wid = tid >> 5;
    int lane = tid & 31;
    int gr = lane >> 2;      // group row 0..7
    int gc = lane & 3;       // col-in-group 0..3
    int bm = blockIdx.y * 128, bn = blockIdx.x * 128;
    int m0 = (wid & 1) * 64;      // warp m-offset
    int n0 = (wid >> 1) * 32;     // warp n-offset

    float acc[4][4][4];
#pragma unroll
    for (int mt = 0; mt < 4; mt++)
#pragma unroll
        for (int nt = 0; nt < 4; nt++)
#pragma unroll
            for (int i = 0; i < 4; i++) acc[mt][nt][i] = 0.f;

    const int crow = tid >> 3;        // 0..31 (row within 32-row slab)
    const int ccol = (tid & 7) * 4;   // float col 0..28

    for (int kc = 0; kc < K; kc += 32) {
        // ---- stage A/B chunk, converting to tf32 ----
#pragma unroll
        for (int i = 0; i < 4; i++) {
            int row = i * 32 + crow;
            float4 va = *(const float4*)(A  + (size_t)(bm + row) * K + kc + ccol);
            float4 vb = *(const float4*)(BT + (size_t)(bn + row) * K + kc + ccol);
            uint4 ta = { f2tf32(va.x), f2tf32(va.y), f2tf32(va.z), f2tf32(va.w) };
            uint4 tb = { f2tf32(vb.x), f2tf32(vb.y), f2tf32(vb.z), f2tf32(vb.w) };
            *(uint4*)&As[row * SMS + ccol] = ta;
            *(uint4*)&Bs[row * SMS + ccol] = tb;
        }
        __syncthreads();

        // ---- 4 k8 steps ----
#pragma unroll
        for (int ks = 0; ks < 4; ks++) {
            int k0 = ks * 8;
            uint32_t af[4][4], bf[4][2];
#pragma unroll
            for (int mt = 0; mt < 4; mt++) {
                const float* base = &As[(m0 + mt * 16 + gr) * SMS + k0 + gc];
                af[mt][0] = __float_as_uint(base[0]);
                af[mt][1] = __float_as_uint(base[8 * SMS]);
                af[mt][2] = __float_as_uint(base[4]);
                af[mt][3] = __float_as_uint(base[8 * SMS + 4]);
            }
#pragma unroll
            for (int nt = 0; nt < 4; nt++) {
                const float* base = &Bs[(n0 + nt * 8 + gr) * SMS + k0 + gc];
                bf[nt][0] = __float_as_uint(base[0]);
                bf[nt][1] = __float_as_uint(base[4]);
            }
#pragma unroll
            for (int mt = 0; mt < 4; mt++)
#pragma unroll
                for (int nt = 0; nt < 4; nt++)
                    mma_tf32(acc[mt][nt], af[mt], bf[nt]);
        }
        __syncthreads();
    }

    // ---- epilogue: direct float2 stores ----
#pragma unroll
    for (int mt = 0; mt < 4; mt++) {
#pragma unroll
        for (int nt = 0; nt < 4; nt++) {
            int row = bm + m0 + mt * 16 + gr;
            int col = bn + n0 + nt * 8 + 2 * gc;
            *(float2*)&C[(size_t)row * N + col] =
                make_float2(acc[mt][nt][0], acc[mt][nt][1]);
            *(float2*)&C[(size_t)(row + 8) * N + col] =
                make_float2(acc[mt][nt][2], acc[mt][nt][3]);
        }
    }
}

// ============================================================
// RoPE + RMSNorm, one warp per (row, head). In-place on Q and K.
// ============================================================
__global__ __launch_bounds__(256) void rope_rms(
    float* __restrict__ Q, float* __restrict__ K,
    const float* __restrict__ cosp, const float* __restrict__ sinp)
{
    int gw = (blockIdx.x * blockDim.x + threadIdx.x) >> 5;
    int lane = threadIdx.x & 31;
    const int total_q = Bsz * Tt * Hh;

    float* p;
    int t;
    if (gw < total_q) {
        t = (gw / Hh) % Tt;
        p = Q + (size_t)gw * HDim;
    } else {
        int g = gw - total_q;
        t = (g / KVh) % Tt;
        p = K + (size_t)g * HDim;
    }

    float c = cosp[t * (HDim / 2) + lane];
    float s = sinp[t * (HDim / 2) + lane];
    float x1 = p[lane];
    float x2 = p[lane + 32];
    float o1 = x1 * c + x2 * s;
    float o2 = -x1 * s + x2 * c;

    float ss = o1 * o1 + o2 * o2;
#pragma unroll
    for (int off = 16; off > 0; off >>= 1)
        ss += __shfl_xor_sync(0xffffffffu, ss, off);

    float inv = rsqrtf(ss * (1.0f / HDim) + 1e-6f);
    p[lane]      = o1 * inv;
    p[lane + 32] = o2 * inv;
}

// ============================================================
// Causal GQA flash attention (scalar, unchanged this round)
// ============================================================
__global__ __launch_bounds__(64) void flash_attn(
    const float* __restrict__ Qg, const float* __restrict__ Kg,
    const float* __restrict__ Vg, float* __restrict__ Og)
{
    __shared__ float Ks[64 * 64];
    __shared__ float Vs[64 * 64];
    __shared__ float Ss[64 * 64];

    int qb = blockIdx.x;
    int h  = blockIdx.y;
    int b  = blockIdx.z;
    int t  = threadIdx.x;
    int kvh = h >> 2;
    int q0 = qb * 64;

    const float* Qbase = Qg + ((size_t)(b * Tt + q0) * Hh + h) * HDim;
#pragma unroll
    for (int i = 0; i < 16; i++) {
        int fi = i * 64 + t;
        int row = fi >> 4, c4 = fi & 15;
        *(float4*)&Ss[row * 64 + c4 * 4] =
            *(const float4*)(Qbase + (size_t)row * (Hh * HDim) + c4 * 4);
    }
    __syncthreads();

    float4 q[16];
#pragma unroll
    for (int i = 0; i < 16; i++) q[i] = *(const float4*)&Ss[t * 64 + i * 4];
    __syncthreads();

    float4 o[16];
#pragma unroll
    for (int i = 0; i < 16; i++) o[i] = make_float4(0.f, 0.f, 0.f, 0.f);
    float m = -1e30f, l = 0.f;

    const float* Kbase = Kg + ((size_t)(b * Tt) * KVh + kvh) * HDim;
    const float* Vbase = Vg + ((size_t)(b * Tt) * KVh + kvh) * HDim;

    for (int kt = 0; kt <= qb; kt++) {
#pragma unroll
        for (int i = 0; i < 16; i++) {
            int fi = i * 64 + t;
            int row = fi >> 4, c4 = fi & 15;
            size_t g = (size_t)(kt * 64 + row) * (KVh * HDim) + c4 * 4;
            *(float4*)&Ks[row * 64 + c4 * 4] = *(const float4*)(Kbase + g);
            *(float4*)&Vs[row * 64 + c4 * 4] = *(const float4*)(Vbase + g);
        }
        __syncthreads();

        int jmax = (kt == qb) ? t : 63;
        float tmax = -1e30f;

        for (int j = 0; j < 64; j++) {
            float s;
            if (j <= jmax) {
                float a0 = 0.f, a1 = 0.f, a2 = 0.f, a3 = 0.f;
                const float4* kr = (const float4*)(Ks + j * 64);
#pragma unroll
                for (int i = 0; i < 16; i++) {
                    float4 k4 = kr[i];
                    a0 += q[i].x * k4.x;
                    a1 += q[i].y * k4.y;
                    a2 += q[i].z * k4.z;
                    a3 += q[i].w * k4.w;
                }
                s = ((a0 + a1) + (a2 + a3)) * 0.125f;
                tmax = fmaxf(tmax, s);
            } else {
                s = -1e30f;
            }
            Ss[j * 64 + t] = s;
        }

        float mn = fmaxf(m, tmax);
        float corr = __expf(m - mn);
        m = mn;
        l *= corr;
#pragma unroll
        for (int i = 0; i < 16; i++) {
            o[i].x *= corr; o[i].y *= corr; o[i].z *= corr; o[i].w *= corr;
        }

        for (int j = 0; j <= jmax; j++) {
            float p = __expf(Ss[j * 64 + t] - mn);
            l += p;
            const float4* vr = (const float4*)(Vs + j * 64);
#pragma unroll
            for (int i = 0; i < 16; i++) {
                float4 v4 = vr[i];
                o[i].x += p * v4.x;
                o[i].y += p * v4.y;
                o[i].z += p * v4.z;
                o[i].w += p * v4.w;
            }
        }
        __syncthreads();
    }

    float inv = 1.f / l;
#pragma unroll
    for (int i = 0; i < 16; i++) {
        o[i].x *= inv; o[i].y *= inv; o[i].z *= inv; o[i].w *= inv;
        *(float4*)&Ss[t * 64 + i * 4] = o[i];
    }
    __syncthreads();

    float* Obase = Og + ((size_t)(b * Tt + q0) * Hh + h) * HDim;
#pragma unroll
    for (int i = 0; i < 16; i++) {
        int fi = i * 64 + t;
        int row = fi >> 4, c4 = fi & 15;
        *(float4*)(Obase + (size_t)row * (Hh * HDim) + c4 * 4) =
            *(const float4*)&Ss[row * 64 + c4 * 4];
    }
}

// ============================================================
// launch
// ============================================================
extern "C" void kernel_launch(void* const* d_in, const int* in_sizes, int n_in,
                              void* d_out, int out_size)
{
    const float* x  = (const float*)d_in[0];
    const float* cs = (const float*)d_in[1];
    const float* sn = (const float*)d_in[2];
    const float* Wq = (const float*)d_in[3];
    const float* Wk = (const float*)d_in[4];
    const float* Wv = (const float*)d_in[5];
    const float* Wo = (const float*)d_in[6];
    float* out = (float*)d_out;

    float *Qp, *Kp, *Vp, *Yp, *WqT, *WkT, *WvT, *WoT;
    cudaGetSymbolAddress((void**)&Qp, g_Q);
    cudaGetSymbolAddress((void**)&Kp, g_K);
    cudaGetSymbolAddress((void**)&Vp, g_V);
    cudaGetSymbolAddress((void**)&Yp, g_Y);
    cudaGetSymbolAddress((void**)&WqT, g_WqT);
    cudaGetSymbolAddress((void**)&WkT, g_WkT);
    cudaGetSymbolAddress((void**)&WvT, g_WvT);
    cudaGetSymbolAddress((void**)&WoT, g_WoT);

    const int M = Bsz * Tt;  // 4096

    // weight transposes (W[K,N] -> WT[N,K])
    transpose_k<<<dim3(Hh * HDim / 32, Cc / 32), dim3(32, 8)>>>(Wq, WqT, Cc, Hh * HDim);
    transpose_k<<<dim3(KVh * HDim / 32, Cc / 32), dim3(32, 8)>>>(Wk, WkT, Cc, KVh * HDim);
    transpose_k<<<dim3(KVh * HDim / 32, Cc / 32), dim3(32, 8)>>>(Wv, WvT, Cc, KVh * HDim);
    transpose_k<<<dim3(Cc / 32, Cc / 32), dim3(32, 8)>>>(Wo, WoT, Cc, Cc);

    // QKV projections (tf32 mma.sync)
    gemm_mma<<<dim3(Hh * HDim / 128, M / 128), 256>>>(x, WqT, Qp, M, Hh * HDim, Cc);
    gemm_mma<<<dim3(KVh * HDim / 128, M / 128), 256>>>(x, WkT, Kp, M, KVh * HDim, Cc);
    gemm_mma<<<dim3(KVh * HDim / 128, M / 128), 256>>>(x, WvT, Vp, M, KVh * HDim, Cc);

    // RoPE + RMSNorm on Q and K
    {
        int warps = M * (Hh + KVh);
        int threads = warps * 32;
        rope_rms<<<threads / 256, 256>>>(Qp, Kp, cs, sn);
    }

    // causal GQA flash attention
    flash_attn<<<dim3(Tt / 64, Hh, Bsz), 64>>>(Qp, Kp, Vp, Yp);

    // output projection (tf32 mma.sync)
    gemm_mma<<<dim3(Cc / 128, M / 128), 256>>>(Yp, WoT, out, M, Cc, Cc);
}

// round 4
// speedup vs baseline: 3.5144x; 2.4198x over previous
#include <cuda_runtime.h>
#include <math.h>
#include <stdint.h>

#define Bsz 2
#define Tt  2048
#define Cc  1024
#define Hh  16
#define KVh 4
#define HDim 64

// -------- scratch (static device globals; no allocation) --------
__device__ float g_Q[Bsz * Tt * Hh * HDim];
__device__ float g_K[Bsz * Tt * KVh * HDim];
__device__ float g_V[Bsz * Tt * KVh * HDim];
__device__ float g_Y[Bsz * Tt * Hh * HDim];
__device__ float g_WqT[Cc * Hh * HDim];
__device__ float g_WkT[Cc * KVh * HDim];
__device__ float g_WvT[Cc * KVh * HDim];
__device__ float g_WoT[Cc * Cc];

__device__ __forceinline__ uint32_t f2tf32(float f) {
    uint32_t r;
    asm("cvt.rna.tf32.f32 %0, %1;" : "=r"(r) : "f"(f));
    return r;
}
__device__ __forceinline__ float tf(float f) { return __uint_as_float(f2tf32(f)); }

__device__ __forceinline__ void mma_tf32(float* c, const uint32_t* a, const uint32_t* b) {
    asm volatile(
        "mma.sync.aligned.m16n8k8.row.col.f32.tf32.tf32.f32 "
        "{%0,%1,%2,%3}, {%4,%5,%6,%7}, {%8,%9}, {%0,%1,%2,%3};"
        : "+f"(c[0]), "+f"(c[1]), "+f"(c[2]), "+f"(c[3])
        : "r"(a[0]), "r"(a[1]), "r"(a[2]), "r"(a[3]), "r"(b[0]), "r"(b[1]));
}

// ============================================================
// Weight transpose: in[K,N] -> out[N,K]
// ============================================================
__global__ __launch_bounds__(256) void transpose_k(
    const float* __restrict__ in, float* __restrict__ out, int K, int N)
{
    __shared__ float tile[32][33];
    int k0 = blockIdx.y * 32, n0 = blockIdx.x * 32;
    int tx = threadIdx.x, ty = threadIdx.y;
#pragma unroll
    for (int i = 0; i < 32; i += 8)
        tile[ty + i][tx] = in[(size_t)(k0 + ty + i) * N + n0 + tx];
    __syncthreads();
#pragma unroll
    for (int i = 0; i < 32; i += 8)
        out[(size_t)(n0 + ty + i) * K + k0 + tx] = tile[tx][ty + i];
}

// ============================================================
// tf32 mma.sync GEMM: C[M,N] = A[M,K] @ BT[N,K]^T (unchanged)
// ============================================================
#define SMS 36

__global__ __launch_bounds__(256, 2) void gemm_mma(
    const float* __restrict__ A, const float* __restrict__ BT,
    float* __restrict__ C, int M, int N, int K)
{
    __shared__ float As[128 * SMS];
    __shared__ float Bs[128 * SMS];

    int tid = threadIdx.x;
    int wid = tid >> 5;
    int lane = tid & 31;
    int gr = lane >> 2;
    int gc = lane & 3;
    int bm = blockIdx.y * 128, bn = blockIdx.x * 128;
    int m0 = (wid & 1) * 64;
    int n0 = (wid >> 1) * 32;

    float acc[4][4][4];
#pragma unroll
    for (int mt = 0; mt < 4; mt++)
#pragma unroll
        for (int nt = 0; nt < 4; nt++)
#pragma unroll
            for (int i = 0; i < 4; i++) acc[mt][nt][i] = 0.f;

    const int crow = tid >> 3;
    const int ccol = (tid & 7) * 4;

    for (int kc = 0; kc < K; kc += 32) {
#pragma unroll
        for (int i = 0; i < 4; i++) {
            int row = i * 32 + crow;
            float4 va = *(const float4*)(A  + (size_t)(bm + row) * K + kc + ccol);
            float4 vb = *(const float4*)(BT + (size_t)(bn + row) * K + kc + ccol);
            uint4 ta = { f2tf32(va.x), f2tf32(va.y), f2tf32(va.z), f2tf32(va.w) };
            uint4 tb = { f2tf32(vb.x), f2tf32(vb.y), f2tf32(vb.z), f2tf32(vb.w) };
            *(uint4*)&As[row * SMS + ccol] = ta;
            *(uint4*)&Bs[row * SMS + ccol] = tb;
        }
        __syncthreads();

#pragma unroll
        for (int ks = 0; ks < 4; ks++) {
            int k0 = ks * 8;
            uint32_t af[4][4], bf[4][2];
#pragma unroll
            for (int mt = 0; mt < 4; mt++) {
                const float* base = &As[(m0 + mt * 16 + gr) * SMS + k0 + gc];
                af[mt][0] = __float_as_uint(base[0]);
                af[mt][1] = __float_as_uint(base[8 * SMS]);
                af[mt][2] = __float_as_uint(base[4]);
                af[mt][3] = __float_as_uint(base[8 * SMS + 4]);
            }
#pragma unroll
            for (int nt = 0; nt < 4; nt++) {
                const float* base = &Bs[(n0 + nt * 8 + gr) * SMS + k0 + gc];
                bf[nt][0] = __float_as_uint(base[0]);
                bf[nt][1] = __float_as_uint(base[4]);
            }
#pragma unroll
            for (int mt = 0; mt < 4; mt++)
#pragma unroll
                for (int nt = 0; nt < 4; nt++)
                    mma_tf32(acc[mt][nt], af[mt], bf[nt]);
        }
        __syncthreads();
    }

#pragma unroll
    for (int mt = 0; mt < 4; mt++) {
#pragma unroll
        for (int nt = 0; nt < 4; nt++) {
            int row = bm + m0 + mt * 16 + gr;
            int col = bn + n0 + nt * 8 + 2 * gc;
            *(float2*)&C[(size_t)row * N + col] =
                make_float2(acc[mt][nt][0], acc[mt][nt][1]);
            *(float2*)&C[(size_t)(row + 8) * N + col] =
                make_float2(acc[mt][nt][2], acc[mt][nt][3]);
        }
    }
}

// ============================================================
// RoPE + RMSNorm (unchanged)
// ============================================================
__global__ __launch_bounds__(256) void rope_rms(
    float* __restrict__ Q, float* __restrict__ K,
    const float* __restrict__ cosp, const float* __restrict__ sinp)
{
    int gw = (blockIdx.x * blockDim.x + threadIdx.x) >> 5;
    int lane = threadIdx.x & 31;
    const int total_q = Bsz * Tt * Hh;

    float* p;
    int t;
    if (gw < total_q) {
        t = (gw / Hh) % Tt;
        p = Q + (size_t)gw * HDim;
    } else {
        int g = gw - total_q;
        t = (g / KVh) % Tt;
        p = K + (size_t)g * HDim;
    }

    float c = cosp[t * (HDim / 2) + lane];
    float s = sinp[t * (HDim / 2) + lane];
    float x1 = p[lane];
    float x2 = p[lane + 32];
    float o1 = x1 * c + x2 * s;
    float o2 = -x1 * s + x2 * c;

    float ss = o1 * o1 + o2 * o2;
#pragma unroll
    for (int off = 16; off > 0; off >>= 1)
        ss += __shfl_xor_sync(0xffffffffu, ss, off);

    float inv = rsqrtf(ss * (1.0f / HDim) + 1e-6f);
    p[lane]      = o1 * inv;
    p[lane + 32] = o2 * inv;
}

// ============================================================
// tf32 mma.sync causal GQA flash attention.
// grid = (T/128, H, B), 256 threads (8 warps x 16 q-rows).
// K-tiles of 64. Smem stride 68 floats -> conflict-free frags.
// ============================================================
#define AST 68   // smem row stride (floats); 68 % 32 == 4

__global__ __launch_bounds__(256) void flash_attn_mma(
    const float* __restrict__ Qg, const float* __restrict__ Kg,
    const float* __restrict__ Vg, float* __restrict__ Og)
{
    extern __shared__ float sm[];
    float* Qs = sm;                  // 128*AST, reused as Ps
    float* Ks = sm + 128 * AST;      // 64*AST
    float* Vs = Ks + 64 * AST;       // 64*AST

    int qb = blockIdx.x, h = blockIdx.y, b = blockIdx.z;
    int q0 = qb * 128;
    int kvh = h >> 2;
    int tid = threadIdx.x, wid = tid >> 5, lane = tid & 31;
    int gr = lane >> 2, gc = lane & 3;
    int m0 = wid * 16;

    // ---- stage Q (scaled by 1/8, tf32) ----
    const float* Qbase = Qg + ((size_t)(b * Tt + q0) * Hh + h) * HDim;
#pragma unroll
    for (int i = 0; i < 8; i++) {
        int fi = i * 256 + tid;
        int row = fi >> 4, c4 = (fi & 15) * 4;
        float4 v = *(const float4*)(Qbase + (size_t)row * (Hh * HDim) + c4);
        float* d = &Qs[row * AST + c4];
        d[0] = tf(v.x * 0.125f); d[1] = tf(v.y * 0.125f);
        d[2] = tf(v.z * 0.125f); d[3] = tf(v.w * 0.125f);
    }
    __syncthreads();

    // ---- Q fragments (held all loop) ----
    uint32_t qf[8][4];
#pragma unroll
    for (int ks = 0; ks < 8; ks++) {
        const float* p0 = &Qs[(m0 + gr) * AST + ks * 8 + gc];
        qf[ks][0] = __float_as_uint(p0[0]);
        qf[ks][1] = __float_as_uint(p0[8 * AST]);
        qf[ks][2] = __float_as_uint(p0[4]);
        qf[ks][3] = __float_as_uint(p0[8 * AST + 4]);
    }

    float o[8][4];
#pragma unroll
    for (int nt = 0; nt < 8; nt++)
#pragma unroll
        for (int i = 0; i < 4; i++) o[nt][i] = 0.f;
    float m_lo = -1e30f, m_hi = -1e30f, l_lo = 0.f, l_hi = 0.f;

    const int row_lo = q0 + m0 + gr;
    const int row_hi = row_lo + 8;
    const int nkt = 2 * qb + 2;

    for (int kt = 0; kt < nkt; kt++) {
        int kv0 = kt * 64;
        __syncthreads();   // protect Ks/Vs/Ps from previous iteration readers

        // ---- stage K, V tiles (tf32) ----
        const float* Kbase = Kg + ((size_t)(b * Tt + kv0) * KVh + kvh) * HDim;
        const float* Vbase = Vg + ((size_t)(b * Tt + kv0) * KVh + kvh) * HDim;
#pragma unroll
        for (int i = 0; i < 4; i++) {
            int fi = i * 256 + tid;
            int row = fi >> 4, c4 = (fi & 15) * 4;
            size_t g = (size_t)row * (KVh * HDim) + c4;
            float4 kv = *(const float4*)(Kbase + g);
            float4 vv = *(const float4*)(Vbase + g);
            float* dk = &Ks[row * AST + c4];
            float* dv = &Vs[row * AST + c4];
            dk[0] = tf(kv.x); dk[1] = tf(kv.y); dk[2] = tf(kv.z); dk[3] = tf(kv.w);
            dv[0] = tf(vv.x); dv[1] = tf(vv.y); dv[2] = tf(vv.z); dv[3] = tf(vv.w);
        }
        __syncthreads();

        // ---- S = Q K^T ----
        float s[8][4];
#pragma unroll
        for (int nt = 0; nt < 8; nt++)
#pragma unroll
            for (int i = 0; i < 4; i++) s[nt][i] = 0.f;

#pragma unroll
        for (int ks = 0; ks < 8; ks++) {
#pragma unroll
            for (int nt = 0; nt < 8; nt++) {
                uint32_t bf[2];
                const float* bp = &Ks[(nt * 8 + gr) * AST + ks * 8 + gc];
                bf[0] = __float_as_uint(bp[0]);
                bf[1] = __float_as_uint(bp[4]);
                mma_tf32(s[nt], qf[ks], bf);
            }
        }

        // ---- causal mask (diagonal tiles only) ----
        if (kv0 + 63 > q0) {
#pragma unroll
            for (int nt = 0; nt < 8; nt++) {
                int c0 = kv0 + nt * 8 + 2 * gc;
                if (c0 > row_lo)     s[nt][0] = -1e30f;
                if (c0 + 1 > row_lo) s[nt][1] = -1e30f;
                if (c0 > row_hi)     s[nt][2] = -1e30f;
                if (c0 + 1 > row_hi) s[nt][3] = -1e30f;
            }
        }

        // ---- online softmax ----
        float tlo = -1e30f, thi = -1e30f;
#pragma unroll
        for (int nt = 0; nt < 8; nt++) {
            tlo = fmaxf(tlo, fmaxf(s[nt][0], s[nt][1]));
            thi = fmaxf(thi, fmaxf(s[nt][2], s[nt][3]));
        }
        tlo = fmaxf(tlo, __shfl_xor_sync(0xffffffffu, tlo, 1));
        tlo = fmaxf(tlo, __shfl_xor_sync(0xffffffffu, tlo, 2));
        thi = fmaxf(thi, __shfl_xor_sync(0xffffffffu, thi, 1));
        thi = fmaxf(thi, __shfl_xor_sync(0xffffffffu, thi, 2));

        float mn_lo = fmaxf(m_lo, tlo);
        float mn_hi = fmaxf(m_hi, thi);
        float cor_lo = __expf(m_lo - mn_lo);
        float cor_hi = __expf(m_hi - mn_hi);
        m_lo = mn_lo; m_hi = mn_hi;
        l_lo *= cor_lo; l_hi *= cor_hi;
#pragma unroll
        for (int nt = 0; nt < 8; nt++) {
            o[nt][0] *= cor_lo; o[nt][1] *= cor_lo;
            o[nt][2] *= cor_hi; o[nt][3] *= cor_hi;
        }

        // ---- P = exp(S - m), store to smem (tf32) ----
        float* Ps = Qs;
#pragma unroll
        for (int nt = 0; nt < 8; nt++) {
            float p0 = __expf(s[nt][0] - m_lo);
            float p1 = __expf(s[nt][1] - m_lo);
            float p2 = __expf(s[nt][2] - m_hi);
            float p3 = __expf(s[nt][3] - m_hi);
            l_lo += p0 + p1;
            l_hi += p2 + p3;
            *(float2*)&Ps[(m0 + gr) * AST + nt * 8 + 2 * gc] =
                make_float2(tf(p0), tf(p1));
            *(float2*)&Ps[(m0 + 8 + gr) * AST + nt * 8 + 2 * gc] =
                make_float2(tf(p2), tf(p3));
        }
        __syncthreads();

        // ---- O += P V ----
#pragma unroll
        for (int ks = 0; ks < 8; ks++) {
            uint32_t pa[4];
            const float* pp = &Ps[(m0 + gr) * AST + ks * 8 + gc];
            pa[0] = __float_as_uint(pp[0]);
            pa[1] = __float_as_uint(pp[8 * AST]);
            pa[2] = __float_as_uint(pp[4]);
            pa[3] = __float_as_uint(pp[8 * AST + 4]);
#pragma unroll
            for (int nt = 0; nt < 8; nt++) {
                uint32_t bv[2];
                bv[0] = __float_as_uint(Vs[(ks * 8 + gc) * AST + nt * 8 + gr]);
                bv[1] = __float_as_uint(Vs[(ks * 8 + gc + 4) * AST + nt * 8 + gr]);
                mma_tf32(o[nt], pa, bv);
            }
        }
    }

    // ---- finalize ----
    l_lo += __shfl_xor_sync(0xffffffffu, l_lo, 1);
    l_lo += __shfl_xor_sync(0xffffffffu, l_lo, 2);
    l_hi += __shfl_xor_sync(0xffffffffu, l_hi, 1);
    l_hi += __shfl_xor_sync(0xffffffffu, l_hi, 2);
    float inv_lo = 1.f / l_lo;
    float inv_hi = 1.f / l_hi;

    float* Obase = Og + ((size_t)(b * Tt) * Hh + h) * HDim;
#pragma unroll
    for (int nt = 0; nt < 8; nt++) {
        int col = nt * 8 + 2 * gc;
        *(float2*)&Obase[(size_t)row_lo * (Hh * HDim) + col] =
            make_float2(o[nt][0] * inv_lo, o[nt][1] * inv_lo);
        *(float2*)&Obase[(size_t)row_hi * (Hh * HDim) + col] =
            make_float2(o[nt][2] * inv_hi, o[nt][3] * inv_hi);
    }
}

#define FLASH_SMEM ((128 + 64 + 64) * AST * 4)

// ============================================================
// launch
// ============================================================
extern "C" void kernel_launch(void* const* d_in, const int* in_sizes, int n_in,
                              void* d_out, int out_size)
{
    const float* x  = (const float*)d_in[0];
    const float* cs = (const float*)d_in[1];
    const float* sn = (const float*)d_in[2];
    const float* Wq = (const float*)d_in[3];
    const float* Wk = (const float*)d_in[4];
    const float* Wv = (const float*)d_in[5];
    const float* Wo = (const float*)d_in[6];
    float* out = (float*)d_out;

    float *Qp, *Kp, *Vp, *Yp, *WqT, *WkT, *WvT, *WoT;
    cudaGetSymbolAddress((void**)&Qp, g_Q);
    cudaGetSymbolAddress((void**)&Kp, g_K);
    cudaGetSymbolAddress((void**)&Vp, g_V);
    cudaGetSymbolAddress((void**)&Yp, g_Y);
    cudaGetSymbolAddress((void**)&WqT, g_WqT);
    cudaGetSymbolAddress((void**)&WkT, g_WkT);
    cudaGetSymbolAddress((void**)&WvT, g_WvT);
    cudaGetSymbolAddress((void**)&WoT, g_WoT);

    cudaFuncSetAttribute(flash_attn_mma,
                         cudaFuncAttributeMaxDynamicSharedMemorySize, FLASH_SMEM);

    const int M = Bsz * Tt;  // 4096

    transpose_k<<<dim3(Hh * HDim / 32, Cc / 32), dim3(32, 8)>>>(Wq, WqT, Cc, Hh * HDim);
    transpose_k<<<dim3(KVh * HDim / 32, Cc / 32), dim3(32, 8)>>>(Wk, WkT, Cc, KVh * HDim);
    transpose_k<<<dim3(KVh * HDim / 32, Cc / 32), dim3(32, 8)>>>(Wv, WvT, Cc, KVh * HDim);
    transpose_k<<<dim3(Cc / 32, Cc / 32), dim3(32, 8)>>>(Wo, WoT, Cc, Cc);

    gemm_mma<<<dim3(Hh * HDim / 128, M / 128), 256>>>(x, WqT, Qp, M, Hh * HDim, Cc);
    gemm_mma<<<dim3(KVh * HDim / 128, M / 128), 256>>>(x, WkT, Kp, M, KVh * HDim, Cc);
    gemm_mma<<<dim3(KVh * HDim / 128, M / 128), 256>>>(x, WvT, Vp, M, KVh * HDim, Cc);

    {
        int warps = M * (Hh + KVh);
        int threads = warps * 32;
        rope_rms<<<threads / 256, 256>>>(Qp, Kp, cs, sn);
    }

    flash_attn_mma<<<dim3(Tt / 128, Hh, Bsz), 256, FLASH_SMEM>>>(Qp, Kp, Vp, Yp);

    gemm_mma<<<dim3(Cc / 128, M / 128), 256>>>(Yp, WoT, out, M, Cc, Cc);
}

// round 5
// speedup vs baseline: 4.1651x; 1.1852x over previous
#include <cuda_runtime.h>
#include <math.h>
#include <stdint.h>

#define Bsz 2
#define Tt  2048
#define Cc  1024
#define Hh  16
#define KVh 4
#define HDim 64
#define QKVN 1536   // 1024 Q + 256 K + 256 V

// -------- scratch (static device globals; no allocation) --------
__device__ float g_QKV[Bsz * Tt * QKVN];       // fused Q|K|V rows
__device__ float g_Y[Bsz * Tt * Hh * HDim];
__device__ float g_WqkvT[QKVN * Cc];           // rows 0-1023 Wq^T, 1024-1279 Wk^T, 1280-1535 Wv^T
__device__ float g_WoT[Cc * Cc];

__device__ __forceinline__ uint32_t f2tf32(float f) {
    uint32_t r;
    asm("cvt.rna.tf32.f32 %0, %1;" : "=r"(r) : "f"(f));
    return r;
}
__device__ __forceinline__ float tf(float f) { return __uint_as_float(f2tf32(f)); }

__device__ __forceinline__ void mma_tf32(float* c, const uint32_t* a, const uint32_t* b) {
    asm volatile(
        "mma.sync.aligned.m16n8k8.row.col.f32.tf32.tf32.f32 "
        "{%0,%1,%2,%3}, {%4,%5,%6,%7}, {%8,%9}, {%0,%1,%2,%3};"
        : "+f"(c[0]), "+f"(c[1]), "+f"(c[2]), "+f"(c[3])
        : "r"(a[0]), "r"(a[1]), "r"(a[2]), "r"(a[3]), "r"(b[0]), "r"(b[1]));
}

__device__ __forceinline__ void cpa16(float* s, const float* g) {
    uint32_t sa = (uint32_t)__cvta_generic_to_shared(s);
    asm volatile("cp.async.ca.shared.global [%0], [%1], 16;" :: "r"(sa), "l"(g));
}
#define CP_COMMIT() asm volatile("cp.async.commit_group;" ::: "memory")
#define CP_WAIT(n)  asm volatile("cp.async.wait_group %0;" :: "n"(n) : "memory")

// ============================================================
// Weight transpose: in[K,N] -> out[N,K]
// ============================================================
__global__ __launch_bounds__(256) void transpose_k(
    const float* __restrict__ in, float* __restrict__ out, int K, int N)
{
    __shared__ float tile[32][33];
    int k0 = blockIdx.y * 32, n0 = blockIdx.x * 32;
    int tx = threadIdx.x, ty = threadIdx.y;
#pragma unroll
    for (int i = 0; i < 32; i += 8)
        tile[ty + i][tx] = in[(size_t)(k0 + ty + i) * N + n0 + tx];
    __syncthreads();
#pragma unroll
    for (int i = 0; i < 32; i += 8)
        out[(size_t)(n0 + ty + i) * K + k0 + tx] = tile[tx][ty + i];
}

// ============================================================
// Pipelined tf32 mma.sync GEMM: C[M,N] = A[M,K] @ BT[N,K]^T
// 128x128 CTA tile, 256 threads, K-chunk 32, cp.async 2-stage.
// Smem holds raw fp32; tf32 convert on fragment load.
// ============================================================
#define SMS 36
#define STAGE_F (2 * 128 * SMS)          // floats per stage (A+B)
#define GEMM_SMEM (2 * STAGE_F * 4)      // 73728 bytes

__global__ __launch_bounds__(256, 2) void gemm_mma(
    const float* __restrict__ A, const float* __restrict__ BT,
    float* __restrict__ C, int M, int N, int K)
{
    extern __shared__ float sh[];

    int tid = threadIdx.x;
    int wid = tid >> 5;
    int lane = tid & 31;
    int gr = lane >> 2;
    int gc = lane & 3;
    int bm = blockIdx.y * 128, bn = blockIdx.x * 128;
    int m0 = (wid & 1) * 64;
    int n0 = (wid >> 1) * 32;

    const int crow = tid >> 3;        // 0..31
    const int ccol = (tid & 7) * 4;   // 0..28

    float acc[4][4][4];
#pragma unroll
    for (int mt = 0; mt < 4; mt++)
#pragma unroll
        for (int nt = 0; nt < 4; nt++)
#pragma unroll
            for (int i = 0; i < 4; i++) acc[mt][nt][i] = 0.f;

    auto issue = [&](int s, int kc) {
        float* As = sh + s * STAGE_F;
        float* Bs = As + 128 * SMS;
#pragma unroll
        for (int i = 0; i < 4; i++) {
            int row = i * 32 + crow;
            cpa16(&As[row * SMS + ccol], A  + (size_t)(bm + row) * K + kc + ccol);
            cpa16(&Bs[row * SMS + ccol], BT + (size_t)(bn + row) * K + kc + ccol);
        }
        CP_COMMIT();
    };

    issue(0, 0);

    const int NCH = K / 32;
    for (int c = 0; c < NCH; c++) {
        int s = c & 1;
        if (c + 1 < NCH) { issue(s ^ 1, (c + 1) * 32); CP_WAIT(1); }
        else             { CP_WAIT(0); }
        __syncthreads();

        const float* As = sh + s * STAGE_F;
        const float* Bs = As + 128 * SMS;
#pragma unroll
        for (int ks = 0; ks < 4; ks++) {
            int k0 = ks * 8;
            uint32_t af[4][4], bf[4][2];
#pragma unroll
            for (int mt = 0; mt < 4; mt++) {
                const float* base = &As[(m0 + mt * 16 + gr) * SMS + k0 + gc];
                af[mt][0] = f2tf32(base[0]);
                af[mt][1] = f2tf32(base[8 * SMS]);
                af[mt][2] = f2tf32(base[4]);
                af[mt][3] = f2tf32(base[8 * SMS + 4]);
            }
#pragma unroll
            for (int nt = 0; nt < 4; nt++) {
                const float* base = &Bs[(n0 + nt * 8 + gr) * SMS + k0 + gc];
                bf[nt][0] = f2tf32(base[0]);
                bf[nt][1] = f2tf32(base[4]);
            }
#pragma unroll
            for (int mt = 0; mt < 4; mt++)
#pragma unroll
                for (int nt = 0; nt < 4; nt++)
                    mma_tf32(acc[mt][nt], af[mt], bf[nt]);
        }
        __syncthreads();
    }

#pragma unroll
    for (int mt = 0; mt < 4; mt++) {
#pragma unroll
        for (int nt = 0; nt < 4; nt++) {
            int row = bm + m0 + mt * 16 + gr;
            int col = bn + n0 + nt * 8 + 2 * gc;
            *(float2*)&C[(size_t)row * N + col] =
                make_float2(acc[mt][nt][0], acc[mt][nt][1]);
            *(float2*)&C[(size_t)(row + 8) * N + col] =
                make_float2(acc[mt][nt][2], acc[mt][nt][3]);
        }
    }
}

// ============================================================
// RoPE + RMSNorm over fused QKV buffer (stride QKVN).
// ============================================================
__global__ __launch_bounds__(256) void rope_rms(
    float* __restrict__ QKV,
    const float* __restrict__ cosp, const float* __restrict__ sinp)
{
    int gw = (blockIdx.x * blockDim.x + threadIdx.x) >> 5;
    int lane = threadIdx.x & 31;
    const int total_q = Bsz * Tt * Hh;

    float* p;
    int t;
    if (gw < total_q) {
        int bt = gw / Hh, h = gw % Hh;
        t = bt % Tt;
        p = QKV + (size_t)bt * QKVN + h * HDim;
    } else {
        int g = gw - total_q;
        int bt = g / KVh, kv = g % KVh;
        t = bt % Tt;
        p = QKV + (size_t)bt * QKVN + 1024 + kv * HDim;
    }

    float c = cosp[t * (HDim / 2) + lane];
    float s = sinp[t * (HDim / 2) + lane];
    float x1 = p[lane];
    float x2 = p[lane + 32];
    float o1 = x1 * c + x2 * s;
    float o2 = -x1 * s + x2 * c;

    float ss = o1 * o1 + o2 * o2;
#pragma unroll
    for (int off = 16; off > 0; off >>= 1)
        ss += __shfl_xor_sync(0xffffffffu, ss, off);

    float inv = rsqrtf(ss * (1.0f / HDim) + 1e-6f);
    p[lane]      = o1 * inv;
    p[lane + 32] = o2 * inv;
}

// ============================================================
// tf32 mma.sync causal GQA flash attention (reads fused QKV).
// grid = (T/128, H, B), 256 threads (8 warps x 16 q-rows).
// ============================================================
#define AST 68

__global__ __launch_bounds__(256) void flash_attn_mma(
    const float* __restrict__ QKV, float* __restrict__ Og)
{
    extern __shared__ float sm[];
    float* Qs = sm;                  // 128*AST, reused as Ps
    float* Ks = sm + 128 * AST;      // 64*AST
    float* Vs = Ks + 64 * AST;       // 64*AST

    int qb = blockIdx.x, h = blockIdx.y, b = blockIdx.z;
    int q0 = qb * 128;
    int kvh = h >> 2;
    int tid = threadIdx.x, wid = tid >> 5, lane = tid & 31;
    int gr = lane >> 2, gc = lane & 3;
    int m0 = wid * 16;

    // ---- stage Q (scaled by 1/8, tf32) ----
    const float* Qbase = QKV + (size_t)(b * Tt + q0) * QKVN + h * HDim;
#pragma unroll
    for (int i = 0; i < 8; i++) {
        int fi = i * 256 + tid;
        int row = fi >> 4, c4 = (fi & 15) * 4;
        float4 v = *(const float4*)(Qbase + (size_t)row * QKVN + c4);
        float* d = &Qs[row * AST + c4];
        d[0] = tf(v.x * 0.125f); d[1] = tf(v.y * 0.125f);
        d[2] = tf(v.z * 0.125f); d[3] = tf(v.w * 0.125f);
    }
    __syncthreads();

    uint32_t qf[8][4];
#pragma unroll
    for (int ks = 0; ks < 8; ks++) {
        const float* p0 = &Qs[(m0 + gr) * AST + ks * 8 + gc];
        qf[ks][0] = __float_as_uint(p0[0]);
        qf[ks][1] = __float_as_uint(p0[8 * AST]);
        qf[ks][2] = __float_as_uint(p0[4]);
        qf[ks][3] = __float_as_uint(p0[8 * AST + 4]);
    }

    float o[8][4];
#pragma unroll
    for (int nt = 0; nt < 8; nt++)
#pragma unroll
        for (int i = 0; i < 4; i++) o[nt][i] = 0.f;
    float m_lo = -1e30f, m_hi = -1e30f, l_lo = 0.f, l_hi = 0.f;

    const int row_lo = q0 + m0 + gr;
    const int row_hi = row_lo + 8;
    const int nkt = 2 * qb + 2;

    for (int kt = 0; kt < nkt; kt++) {
        int kv0 = kt * 64;
        __syncthreads();

        const float* Kbase = QKV + (size_t)(b * Tt + kv0) * QKVN + 1024 + kvh * HDim;
        const float* Vbase = Kbase + 256;
#pragma unroll
        for (int i = 0; i < 4; i++) {
            int fi = i * 256 + tid;
            int row = fi >> 4, c4 = (fi & 15) * 4;
            size_t g = (size_t)row * QKVN + c4;
            float4 kv = *(const float4*)(Kbase + g);
            float4 vv = *(const float4*)(Vbase + g);
            float* dk = &Ks[row * AST + c4];
            float* dv = &Vs[row * AST + c4];
            dk[0] = tf(kv.x); dk[1] = tf(kv.y); dk[2] = tf(kv.z); dk[3] = tf(kv.w);
            dv[0] = tf(vv.x); dv[1] = tf(vv.y); dv[2] = tf(vv.z); dv[3] = tf(vv.w);
        }
        __syncthreads();

        float s[8][4];
#pragma unroll
        for (int nt = 0; nt < 8; nt++)
#pragma unroll
            for (int i = 0; i < 4; i++) s[nt][i] = 0.f;

#pragma unroll
        for (int ks = 0; ks < 8; ks++) {
#pragma unroll
            for (int nt = 0; nt < 8; nt++) {
                uint32_t bf[2];
                const float* bp = &Ks[(nt * 8 + gr) * AST + ks * 8 + gc];
                bf[0] = __float_as_uint(bp[0]);
                bf[1] = __float_as_uint(bp[4]);
                mma_tf32(s[nt], qf[ks], bf);
            }
        }

        if (kv0 + 63 > q0) {
#pragma unroll
            for (int nt = 0; nt < 8; nt++) {
                int c0 = kv0 + nt * 8 + 2 * gc;
                if (c0 > row_lo)     s[nt][0] = -1e30f;
                if (c0 + 1 > row_lo) s[nt][1] = -1e30f;
                if (c0 > row_hi)     s[nt][2] = -1e30f;
                if (c0 + 1 > row_hi) s[nt][3] = -1e30f;
            }
        }

        float tlo = -1e30f, thi = -1e30f;
#pragma unroll
        for (int nt = 0; nt < 8; nt++) {
            tlo = fmaxf(tlo, fmaxf(s[nt][0], s[nt][1]));
            thi = fmaxf(thi, fmaxf(s[nt][2], s[nt][3]));
        }
        tlo = fmaxf(tlo, __shfl_xor_sync(0xffffffffu, tlo, 1));
        tlo = fmaxf(tlo, __shfl_xor_sync(0xffffffffu, tlo, 2));
        thi = fmaxf(thi, __shfl_xor_sync(0xffffffffu, thi, 1));
        thi = fmaxf(thi, __shfl_xor_sync(0xffffffffu, thi, 2));

        float mn_lo = fmaxf(m_lo, tlo);
        float mn_hi = fmaxf(m_hi, thi);
        float cor_lo = __expf(m_lo - mn_lo);
        float cor_hi = __expf(m_hi - mn_hi);
        m_lo = mn_lo; m_hi = mn_hi;
        l_lo *= cor_lo; l_hi *= cor_hi;
#pragma unroll
        for (int nt = 0; nt < 8; nt++) {
            o[nt][0] *= cor_lo; o[nt][1] *= cor_lo;
            o[nt][2] *= cor_hi; o[nt][3] *= cor_hi;
        }

        float* Ps = Qs;
#pragma unroll
        for (int nt = 0; nt < 8; nt++) {
            float p0 = __expf(s[nt][0] - m_lo);
            float p1 = __expf(s[nt][1] - m_lo);
            float p2 = __expf(s[nt][2] - m_hi);
            float p3 = __expf(s[nt][3] - m_hi);
            l_lo += p0 + p1;
            l_hi += p2 + p3;
            *(float2*)&Ps[(m0 + gr) * AST + nt * 8 + 2 * gc] =
                make_float2(tf(p0), tf(p1));
            *(float2*)&Ps[(m0 + 8 + gr) * AST + nt * 8 + 2 * gc] =
                make_float2(tf(p2), tf(p3));
        }
        __syncthreads();

#pragma unroll
        for (int ks = 0; ks < 8; ks++) {
            uint32_t pa[4];
            const float* pp = &Ps[(m0 + gr) * AST + ks * 8 + gc];
            pa[0] = __float_as_uint(pp[0]);
            pa[1] = __float_as_uint(pp[8 * AST]);
            pa[2] = __float_as_uint(pp[4]);
            pa[3] = __float_as_uint(pp[8 * AST + 4]);
#pragma unroll
            for (int nt = 0; nt < 8; nt++) {
                uint32_t bv[2];
                bv[0] = __float_as_uint(Vs[(ks * 8 + gc) * AST + nt * 8 + gr]);
                bv[1] = __float_as_uint(Vs[(ks * 8 + gc + 4) * AST + nt * 8 + gr]);
                mma_tf32(o[nt], pa, bv);
            }
        }
    }

    l_lo += __shfl_xor_sync(0xffffffffu, l_lo, 1);
    l_lo += __shfl_xor_sync(0xffffffffu, l_lo, 2);
    l_hi += __shfl_xor_sync(0xffffffffu, l_hi, 1);
    l_hi += __shfl_xor_sync(0xffffffffu, l_hi, 2);
    float inv_lo = 1.f / l_lo;
    float inv_hi = 1.f / l_hi;

    float* Obase = Og + ((size_t)(b * Tt) * Hh + h) * HDim;
#pragma unroll
    for (int nt = 0; nt < 8; nt++) {
        int col = nt * 8 + 2 * gc;
        *(float2*)&Obase[(size_t)row_lo * (Hh * HDim) + col] =
            make_float2(o[nt][0] * inv_lo, o[nt][1] * inv_lo);
        *(float2*)&Obase[(size_t)row_hi * (Hh * HDim) + col] =
            make_float2(o[nt][2] * inv_hi, o[nt][3] * inv_hi);
    }
}

#define FLASH_SMEM ((128 + 64 + 64) * AST * 4)

// ============================================================
// launch
// ============================================================
extern "C" void kernel_launch(void* const* d_in, const int* in_sizes, int n_in,
                              void* d_out, int out_size)
{
    const float* x  = (const float*)d_in[0];
    const float* cs = (const float*)d_in[1];
    const float* sn = (const float*)d_in[2];
    const float* Wq = (const float*)d_in[3];
    const float* Wk = (const float*)d_in[4];
    const float* Wv = (const float*)d_in[5];
    const float* Wo = (const float*)d_in[6];
    float* out = (float*)d_out;

    float *QKVp, *Yp, *WqkvT, *WoT;
    cudaGetSymbolAddress((void**)&QKVp, g_QKV);
    cudaGetSymbolAddress((void**)&Yp, g_Y);
    cudaGetSymbolAddress((void**)&WqkvT, g_WqkvT);
    cudaGetSymbolAddress((void**)&WoT, g_WoT);

    cudaFuncSetAttribute(gemm_mma,
                         cudaFuncAttributeMaxDynamicSharedMemorySize, GEMM_SMEM);
    cudaFuncSetAttribute(flash_attn_mma,
                         cudaFuncAttributeMaxDynamicSharedMemorySize, FLASH_SMEM);

    const int M = Bsz * Tt;  // 4096

    // transposes into fused WqkvT (rows: 0-1023 Q, 1024-1279 K, 1280-1535 V)
    transpose_k<<<dim3(Hh * HDim / 32, Cc / 32), dim3(32, 8)>>>(Wq, WqkvT, Cc, Hh * HDim);
    transpose_k<<<dim3(KVh * HDim / 32, Cc / 32), dim3(32, 8)>>>(Wk, WqkvT + 1024 * Cc, Cc, KVh * HDim);
    transpose_k<<<dim3(KVh * HDim / 32, Cc / 32), dim3(32, 8)>>>(Wv, WqkvT + 1280 * Cc, Cc, KVh * HDim);
    transpose_k<<<dim3(Cc / 32, Cc / 32), dim3(32, 8)>>>(Wo, WoT, Cc, Cc);

    // fused QKV projection
    gemm_mma<<<dim3(QKVN / 128, M / 128), 256, GEMM_SMEM>>>(x, WqkvT, QKVp, M, QKVN, Cc);

    // RoPE + RMSNorm on Q and K slices
    {
        int warps = M * (Hh + KVh);
        int threads = warps * 32;
        rope_rms<<<threads / 256, 256>>>(QKVp, cs, sn);
    }

    // causal GQA flash attention
    flash_attn_mma<<<dim3(Tt / 128, Hh, Bsz), 256, FLASH_SMEM>>>(QKVp, Yp);

    // output projection
    gemm_mma<<<dim3(Cc / 128, M / 128), 256, GEMM_SMEM>>>(Yp, WoT, out, M, Cc, Cc);
}